// round 1
// baseline (speedup 1.0000x reference)
#include <cuda_runtime.h>

// out[b,o,d,h,w] = bias[o] + sum_{i=d-2..d+2 in [0,10)} sum_{kh,kw}
//                    x[b,i,h+kh-2,w+kw-2] * W[o,i,i-d+2,kh,kw]
//
// Inputs (metadata order): x[32,10,128,128] f32, W[10,10,5,5,5] f32, b[10] f32
// Output: [32,10,10,128,128] f32

#define NB 32
#define NC 10
#define HW 128

// Repacked weights: [d][ip][kh][kw][o], zero where i=d+ip-2 out of range.
__device__ float g_Wr[10 * 5 * 5 * 5 * 10];

__global__ void repack_kernel(const float* __restrict__ W) {
    int idx = blockIdx.x * blockDim.x + threadIdx.x;
    if (idx >= 12500) return;
    int o    = idx % 10;
    int rest = idx / 10;
    int kw = rest % 5; rest /= 5;
    int kh = rest % 5; rest /= 5;
    int ip = rest % 5;
    int d  = rest / 5;
    int i = d + ip - 2;
    float v = 0.0f;
    if (i >= 0 && i < 10)
        v = W[o * 1250 + i * 125 + ip * 25 + kh * 5 + kw];
    g_Wr[idx] = v;
}

// SMEM layout (dynamic):
//   xs: 10 ch x 36 rows x pitch 37  = 13320 floats (conflict-free pitch)
//   ws: 12500 floats (repacked weights)
//   bs: 10 floats (bias)
#define XS_FLOATS (10 * 36 * 37)
#define WS_FLOATS 12500
#define SMEM_FLOATS (XS_FLOATS + WS_FLOATS + 10)

__global__ __launch_bounds__(256, 2) void conv_main(
    const float* __restrict__ x,
    const float* __restrict__ bias,
    float* __restrict__ out)
{
    extern __shared__ float smem[];
    float* xs = smem;
    float* ws = smem + XS_FLOATS;
    float* bs = ws + WS_FLOATS;

    const int b    = blockIdx.x >> 4;    // 32 batches
    const int tile = blockIdx.x & 15;    // 4x4 tiles of 32x32
    const int h0 = (tile >> 2) << 5;
    const int w0 = (tile & 3) << 5;
    const int tid = threadIdx.x;

    // ---- load x tile with halo (rows h0-2..h0+33, cols w0-2..w0+33) ----
    const float* xb = x + b * (NC * HW * HW);
    for (int idx = tid; idx < 10 * 36 * 36; idx += 256) {
        int c   = idx / 1296;
        int rem = idx - c * 1296;
        int r   = rem / 36;
        int col = rem - r * 36;
        int gh = h0 + r - 2;
        int gw = w0 + col - 2;
        float v = 0.0f;
        if ((unsigned)gh < 128u && (unsigned)gw < 128u)
            v = __ldg(xb + c * (HW * HW) + gh * HW + gw);
        xs[(c * 36 + r) * 37 + col] = v;
    }
    // ---- load repacked weights + bias ----
    for (int idx = tid; idx < WS_FLOATS; idx += 256)
        ws[idx] = g_Wr[idx];
    if (tid < 10) bs[tid] = bias[tid];
    __syncthreads();

    // thread -> (hh, ww): 32 rows x 8 strips of 4 pixels
    const int hh = tid >> 3;
    const int ww = (tid & 7) << 2;
    float* outp = out + b * (100 * HW * HW) + (h0 + hh) * HW + (w0 + ww);

    for (int d = 0; d < 10; ++d) {
        float acc[10][4];
        #pragma unroll
        for (int o = 0; o < 10; ++o) {
            float bv = bs[o];
            #pragma unroll
            for (int p = 0; p < 4; ++p) acc[o][p] = bv;
        }

        const int iLo = (d > 2) ? d - 2 : 0;
        const int iHi = (d < 7) ? d + 2 : 9;

        for (int i = iLo; i <= iHi; ++i) {
            const int ip = i - d + 2;
            const float* wbase = ws + (d * 5 + ip) * 5 * 50;       // per-kh stride 50
            const float* xbase = xs + (i * 36 + hh) * 37 + ww;

            for (int kh = 0; kh < 5; ++kh) {
                // 8 consecutive x values cover kw(0..4)+px(0..3)
                float r[8];
                const float* xr = xbase + kh * 37;
                #pragma unroll
                for (int t = 0; t < 8; ++t) r[t] = xr[t];

                const float* wk = wbase + kh * 50;
                #pragma unroll
                for (int kw = 0; kw < 5; ++kw) {
                    float wv[10];
                    const float2* w2 = (const float2*)(wk + kw * 10);  // 8B aligned
                    #pragma unroll
                    for (int p2 = 0; p2 < 5; ++p2) {
                        float2 t = w2[p2];
                        wv[2 * p2]     = t.x;
                        wv[2 * p2 + 1] = t.y;
                    }
                    #pragma unroll
                    for (int o = 0; o < 10; ++o) {
                        #pragma unroll
                        for (int p = 0; p < 4; ++p)
                            acc[o][p] = fmaf(wv[o], r[kw + p], acc[o][p]);
                    }
                }
            }
        }

        // ---- store: float4 per (o,d) ----
        #pragma unroll
        for (int o = 0; o < 10; ++o) {
            float4 v = make_float4(acc[o][0], acc[o][1], acc[o][2], acc[o][3]);
            *(float4*)(outp + (o * 10 + d) * (HW * HW)) = v;
        }
    }
}

extern "C" void kernel_launch(void* const* d_in, const int* in_sizes, int n_in,
                              void* d_out, int out_size) {
    const float* x    = (const float*)d_in[0];
    const float* W    = (const float*)d_in[1];
    const float* bias = (const float*)d_in[2];
    float* out = (float*)d_out;

    repack_kernel<<<49, 256>>>(W);

    const size_t smem_bytes = SMEM_FLOATS * sizeof(float);
    // Idempotent; harmless if it no-ops during graph capture (already set on
    // the first, uncaptured correctness call).
    cudaFuncSetAttribute(conv_main, cudaFuncAttributeMaxDynamicSharedMemorySize,
                         (int)smem_bytes);

    conv_main<<<NB * 16, 256, smem_bytes>>>(x, bias, out);
}

// round 2
// speedup vs baseline: 1.8725x; 1.8725x over previous
#include <cuda_runtime.h>

// out[b,o,d,h,w] = bias[o] + sum_{i=d-2..d+2 in [0,10)} sum_{kh,kw}
//                    x[b,i,h+kh-2,w+kw-2] * W[o,i,i-d+2,kh,kw]
//
// Inputs: x[32,10,128,128] f32, W[10,10,5,5,5] f32, b[10] f32
// Output: [32,10,10,128,128] f32
//
// R2: packed fp32 FMA (fma.rn.f32x2) pairing adjacent output channels.
// Weight pairs (w[o],w[o+1]) load directly as LDS.64 from the o-contiguous
// repacked layout; x values are lane-duplicated once per (i,kh).

#define NB 32
#define NC 10
#define HW 128

typedef unsigned long long u64;

#define FMA2(d_, a_, b_, c_) \
    asm("fma.rn.f32x2 %0, %1, %2, %3;" : "=l"(d_) : "l"(a_), "l"(b_), "l"(c_))
#define PACK2(out_, lo_, hi_) \
    asm("mov.b64 %0, {%1, %2};" : "=l"(out_) : "f"(lo_), "f"(hi_))
#define UNPACK2(lo_, hi_, in_) \
    asm("mov.b64 {%0, %1}, %2;" : "=f"(lo_), "=f"(hi_) : "l"(in_))

// Repacked weights: [d][ip][kh][kw][o], zero where i=d+ip-2 out of range.
__device__ float g_Wr[10 * 5 * 5 * 5 * 10];

__global__ void repack_kernel(const float* __restrict__ W) {
    int idx = blockIdx.x * blockDim.x + threadIdx.x;
    if (idx >= 12500) return;
    int o    = idx % 10;
    int rest = idx / 10;
    int kw = rest % 5; rest /= 5;
    int kh = rest % 5; rest /= 5;
    int ip = rest % 5;
    int d  = rest / 5;
    int i = d + ip - 2;
    float v = 0.0f;
    if (i >= 0 && i < 10)
        v = W[o * 1250 + i * 125 + ip * 25 + kh * 5 + kw];
    g_Wr[idx] = v;
}

// SMEM: xs 10ch x 36 x pitch37 | ws 12500 | bs 10
#define XS_FLOATS (10 * 36 * 37)
#define WS_FLOATS 12500
#define SMEM_FLOATS (XS_FLOATS + WS_FLOATS + 10)

__global__ __launch_bounds__(256, 2) void conv_main(
    const float* __restrict__ x,
    const float* __restrict__ bias,
    float* __restrict__ out)
{
    extern __shared__ float smem[];
    float* xs = smem;
    float* ws = smem + XS_FLOATS;         // 53280 bytes from base -> 8B aligned
    float* bs = ws + WS_FLOATS;           // +50000 bytes -> 8B aligned

    const int b    = blockIdx.x >> 4;
    const int tile = blockIdx.x & 15;
    const int h0 = (tile >> 2) << 5;
    const int w0 = (tile & 3) << 5;
    const int tid = threadIdx.x;

    // ---- load x tile with halo ----
    const float* xb = x + b * (NC * HW * HW);
    for (int idx = tid; idx < 10 * 36 * 36; idx += 256) {
        int c   = idx / 1296;
        int rem = idx - c * 1296;
        int r   = rem / 36;
        int col = rem - r * 36;
        int gh = h0 + r - 2;
        int gw = w0 + col - 2;
        float v = 0.0f;
        if ((unsigned)gh < 128u && (unsigned)gw < 128u)
            v = __ldg(xb + c * (HW * HW) + gh * HW + gw);
        xs[(c * 36 + r) * 37 + col] = v;
    }
    for (int idx = tid; idx < WS_FLOATS; idx += 256)
        ws[idx] = g_Wr[idx];
    if (tid < 10) bs[tid] = bias[tid];
    __syncthreads();

    const int hh = tid >> 3;
    const int ww = (tid & 7) << 2;
    float* outp = out + b * (100 * HW * HW) + (h0 + hh) * HW + (w0 + ww);

    // bias pairs (o,o+1) packed once
    u64 bp[5];
    {
        const u64* b2 = (const u64*)bs;
        #pragma unroll
        for (int o2 = 0; o2 < 5; ++o2) bp[o2] = b2[o2];
    }

    for (int d = 0; d < 10; ++d) {
        u64 acc[5][4];
        #pragma unroll
        for (int o2 = 0; o2 < 5; ++o2)
            #pragma unroll
            for (int p = 0; p < 4; ++p) acc[o2][p] = bp[o2];

        const int iLo = (d > 2) ? d - 2 : 0;
        const int iHi = (d < 7) ? d + 2 : 9;

        for (int i = iLo; i <= iHi; ++i) {
            const int ip = i - d + 2;
            const float* wbase = ws + (d * 5 + ip) * 250;   // 5kh x 5kw x 10o
            const float* xbase = xs + (i * 36 + hh) * 37 + ww;

            #pragma unroll
            for (int kh = 0; kh < 5; ++kh) {
                const float* xr = xbase + kh * 37;
                float r[8];
                #pragma unroll
                for (int t = 0; t < 8; ++t) r[t] = xr[t];
                u64 rr[8];
                #pragma unroll
                for (int t = 0; t < 8; ++t) PACK2(rr[t], r[t], r[t]);

                const u64* wk2 = (const u64*)(wbase + kh * 50);  // 8B aligned
                #pragma unroll
                for (int kw = 0; kw < 5; ++kw) {
                    u64 w[5];
                    #pragma unroll
                    for (int o2 = 0; o2 < 5; ++o2) w[o2] = wk2[kw * 5 + o2];
                    #pragma unroll
                    for (int o2 = 0; o2 < 5; ++o2) {
                        #pragma unroll
                        for (int p = 0; p < 4; ++p)
                            FMA2(acc[o2][p], w[o2], rr[kw + p], acc[o2][p]);
                    }
                }
            }
        }

        // ---- store: two float4 per o-pair ----
        #pragma unroll
        for (int o2 = 0; o2 < 5; ++o2) {
            float lo0, hi0, lo1, hi1, lo2, hi2, lo3, hi3;
            UNPACK2(lo0, hi0, acc[o2][0]);
            UNPACK2(lo1, hi1, acc[o2][1]);
            UNPACK2(lo2, hi2, acc[o2][2]);
            UNPACK2(lo3, hi3, acc[o2][3]);
            float4 va = make_float4(lo0, lo1, lo2, lo3);
            float4 vb = make_float4(hi0, hi1, hi2, hi3);
            *(float4*)(outp + ((2 * o2) * 10 + d) * (HW * HW))     = va;
            *(float4*)(outp + ((2 * o2 + 1) * 10 + d) * (HW * HW)) = vb;
        }
    }
}

extern "C" void kernel_launch(void* const* d_in, const int* in_sizes, int n_in,
                              void* d_out, int out_size) {
    const float* x    = (const float*)d_in[0];
    const float* W    = (const float*)d_in[1];
    const float* bias = (const float*)d_in[2];
    float* out = (float*)d_out;

    repack_kernel<<<49, 256>>>(W);

    const size_t smem_bytes = SMEM_FLOATS * sizeof(float);
    cudaFuncSetAttribute(conv_main, cudaFuncAttributeMaxDynamicSharedMemorySize,
                         (int)smem_bytes);

    conv_main<<<NB * 16, 256, smem_bytes>>>(x, bias, out);
}